// round 15
// baseline (speedup 1.0000x reference)
#include <cuda_runtime.h>
#include <cuda_fp16.h>
#include <math.h>

#define BB 8
#define CC 256
#define MID 64
#define HH 128
#define WW 128
#define HW 16384

// ---------------- scratch (static device arrays; no allocations) -------------
__device__ __half d_xc[BB*HW*MID];      // compress out, channels-last fp16
__device__ float d_h [BB*32*HW];        // off1 out (gelu'd) [b][32][H][W]
__device__ float d_off[BB*18*HW];       // offsets [b][18][H][W]
__device__ __half d_xd[BB*HW*MID];      // deform out, channels-last fp16
__device__ __half d_wt[9*MID*MID];      // deform weight [k][o][c], fp16
__device__ __half d_we[CC*MID];         // expand weight [n][k], fp16
__device__ float d_part[BB*4*128*2];    // GN partial (sum,sumsq) per (b,g,tile)
__device__ float d_mv[BB*4*2];          // GN (mean, rstd) per (b,g)

__device__ __forceinline__ float gelu_exact(float v) {
    return 0.5f * v * (1.0f + erff(v * 0.70710678118654752440f));
}

__device__ __forceinline__ unsigned packh2(float a, float b) {
    __half2 h = __floats2half2_rn(a, b);
    return *(unsigned*)&h;
}

__device__ __forceinline__ void mma16(float4& d, const unsigned* a, unsigned b0, unsigned b1) {
    asm volatile(
        "mma.sync.aligned.m16n8k16.row.col.f32.f16.f16.f32 "
        "{%0,%1,%2,%3}, {%4,%5,%6,%7}, {%8,%9}, {%0,%1,%2,%3};\n"
        : "+f"(d.x), "+f"(d.y), "+f"(d.z), "+f"(d.w)
        : "r"(a[0]), "r"(a[1]), "r"(a[2]), "r"(a[3]), "r"(b0), "r"(b1));
}

// ------- weight prep (merged): deform transpose + expand convert -------------
__global__ void prep_w_kernel(const float* __restrict__ wd,
                              const float* __restrict__ we) {
    int e = blockIdx.x * 256 + threadIdx.x;           // e < 53248
    if (e < 36864) {
        int k = e >> 12;
        int rem = e & 4095;
        int o = rem >> 6;
        int c = rem & 63;
        d_wt[e] = __float2half(wd[(o*64 + c)*9 + k]);
    } else {
        int i = e - 36864;                            // < 16384
        d_we[i] = __float2half(we[i]);
    }
}

// ------- compress: 1x1 conv 256->64 via fp16 mma (m16n8k16), fp16 out --------
__global__ void compress_mma16(const float* __restrict__ feat,
                               const float* __restrict__ w,
                               const float* __restrict__ bias) {
    __shared__ unsigned Asu[16*132];                  // [k2][m] half2, pad 132
    __shared__ unsigned Bsu[64*20];                   // [n][k2] half2, pad 20
    int b = blockIdx.y;
    int p0 = blockIdx.x * 128;
    int t = threadIdx.x;                              // 256
    int warp = t >> 5, lane = t & 31;
    int g = lane >> 2, tg = lane & 3;
    int wm = warp & 3, wn = warp >> 2;

    float4 acc[2][4];
#pragma unroll
    for (int i = 0; i < 2; ++i)
#pragma unroll
        for (int j = 0; j < 4; ++j) acc[i][j] = make_float4(0.f,0.f,0.f,0.f);

    const float* fb = feat + (size_t)b*CC*HW + p0;
    for (int kb = 0; kb < 8; ++kb) {
        __syncthreads();
#pragma unroll
        for (int i = 0; i < 2; ++i) {
            int idx = t + i*256;                      // < 512
            int k2 = idx >> 5, mg = idx & 31;
            const float* r0 = fb + (size_t)(kb*32 + 2*k2)*HW + mg*4;
            float4 v0 = *(const float4*)r0;
            float4 v1 = *(const float4*)(r0 + HW);
            uint4 pk;
            pk.x = packh2(v0.x, v1.x);
            pk.y = packh2(v0.y, v1.y);
            pk.z = packh2(v0.z, v1.z);
            pk.w = packh2(v0.w, v1.w);
            *(uint4*)(Asu + k2*132 + mg*4) = pk;
        }
#pragma unroll
        for (int i = 0; i < 2; ++i) {
            int idx = t + i*256;                      // < 512
            int kq = idx & 7, n = idx >> 3;
            float4 v = *(const float4*)(w + n*256 + kb*32 + kq*4);
            uint2 pk2;
            pk2.x = packh2(v.x, v.y);
            pk2.y = packh2(v.z, v.w);
            *(uint2*)(Bsu + n*20 + kq*2) = pk2;
        }
        __syncthreads();
#pragma unroll
        for (int ks = 0; ks < 2; ++ks) {
            int kk2 = ks*8;
            unsigned a[2][4];
#pragma unroll
            for (int i = 0; i < 2; ++i) {
                int row = wm*32 + i*16 + g;
                a[i][0] = Asu[(kk2+tg  )*132 + row];
                a[i][1] = Asu[(kk2+tg  )*132 + row + 8];
                a[i][2] = Asu[(kk2+tg+4)*132 + row];
                a[i][3] = Asu[(kk2+tg+4)*132 + row + 8];
            }
#pragma unroll
            for (int j = 0; j < 4; ++j) {
                int col = wn*32 + j*8 + g;
                unsigned b0 = Bsu[col*20 + kk2 + tg];
                unsigned b1 = Bsu[col*20 + kk2 + tg + 4];
                mma16(acc[0][j], a[0], b0, b1);
                mma16(acc[1][j], a[1], b0, b1);
            }
        }
    }
    __half* outb = d_xc + ((size_t)b*HW + p0)*64;
#pragma unroll
    for (int i = 0; i < 2; ++i) {
        int row = wm*32 + i*16 + g;
#pragma unroll
        for (int j = 0; j < 4; ++j) {
            int col = wn*32 + j*8 + 2*tg;
            float bx = bias[col], by = bias[col+1];
            *(__half2*)(outb + row*64 + col)     = __floats2half2_rn(acc[i][j].x + bx, acc[i][j].y + by);
            *(__half2*)(outb + (row+8)*64 + col) = __floats2half2_rn(acc[i][j].z + bx, acc[i][j].w + by);
        }
    }
}

// ---------------- off1: 3x3 conv 2->32, pad 1, exact GELU --------------------
__global__ void off1_v2(const float* __restrict__ wind,
                        const float* __restrict__ w,
                        const float* __restrict__ bias) {
    __shared__ float tile[2*3*130];
    __shared__ float wsm[18*32];
    int b = blockIdx.y, y = blockIdx.x;
    int t = threadIdx.x;                              // 128
    for (int e = t; e < 576; e += 128) {
        int co = e / 18, rem = e % 18;
        wsm[rem*32 + co] = w[e];
    }
    for (int e = t; e < 780; e += 128) {
        int ci = e / 390, rem = e % 390;
        int ry = rem / 130, col = rem % 130;
        int yy = y - 1 + ry, xx = col - 1;
        float v = 0.f;
        if (yy >= 0 && yy < HH && xx >= 0 && xx < WW)
            v = wind[(b*2 + ci)*HW + yy*WW + xx];
        tile[e] = v;
    }
    __syncthreads();
    float acc[32];
#pragma unroll
    for (int j = 0; j < 32; ++j) acc[j] = bias[j];
#pragma unroll
    for (int ci = 0; ci < 2; ++ci)
#pragma unroll
        for (int ky = 0; ky < 3; ++ky)
#pragma unroll
            for (int kx = 0; kx < 3; ++kx) {
                float v = tile[ci*390 + ky*130 + t + kx];
                const float* wp = wsm + (ci*9 + ky*3 + kx)*32;
#pragma unroll
                for (int j = 0; j < 32; ++j) acc[j] += v * wp[j];
            }
#pragma unroll
    for (int j = 0; j < 32; ++j)
        d_h[(b*32 + j)*HW + y*WW + t] = gelu_exact(acc[j]);
}

// -- off2 v5: 3x3 conv 32->18, 2px/thread, 9 out-channels/block, grid 512 -----
__global__ void off2_v5(const float* __restrict__ w,
                        const float* __restrict__ bias) {
    __shared__ float wsm[288*12];                     // [(ci*9+kk)][jl] pad 12
    __shared__ float tile[8*6*130];                   // [cil][ry][col]
    int b = blockIdx.y;
    int cs = blockIdx.x & 1;                          // channel half: 9 ch
    int y0 = (blockIdx.x >> 1) * 4;
    int co0 = cs * 9;
    int t = threadIdx.x;                              // 256
    int yp = t >> 7, x = t & 127;

    for (int e = t; e < 2592; e += 256) {             // 288*9
        int jl = e % 9, rem = e / 9;                  // rem < 288 = ci*9+k
        wsm[rem*12 + jl] = w[(co0 + jl)*288 + rem];
    }
    float acc[2][9];
#pragma unroll
    for (int j = 0; j < 9; ++j) {
        acc[0][j] = bias[co0 + j];
        acc[1][j] = bias[co0 + j];
    }

    for (int ch = 0; ch < 4; ++ch) {
        __syncthreads();
        for (int e = t; e < 6240; e += 256) {
            int cil = e / 780, rem = e % 780;
            int ry = rem / 130, col = rem % 130;
            int yy = y0 - 1 + ry, xx = col - 1;
            float v = 0.f;
            if (yy >= 0 && yy < HH && xx >= 0 && xx < WW)
                v = d_h[((b*32 + ch*8 + cil)*HW) + yy*WW + xx];
            tile[e] = v;
        }
        __syncthreads();
        for (int cil = 0; cil < 8; ++cil) {
#pragma unroll
            for (int ky = 0; ky < 3; ++ky) {
                const float* base = tile + cil*780 + (yp*2 + ky)*130 + x;
                float a0 = base[0],   a1 = base[1],   a2 = base[2];
                float b0 = base[130], b1 = base[131], b2 = base[132];
                const float* w0 = wsm + ((ch*8 + cil)*9 + ky*3)*12;
#pragma unroll
                for (int j = 0; j < 9; ++j) {
                    float wa = w0[j], wb = w0[12 + j], wc = w0[24 + j];
                    acc[0][j] += a0*wa + a1*wb + a2*wc;
                    acc[1][j] += b0*wa + b1*wb + b2*wc;
                }
            }
        }
    }
    int ya = y0 + yp*2;
#pragma unroll
    for (int j = 0; j < 9; ++j) {
        d_off[(b*18 + co0 + j)*HW + ya*WW + x]     = acc[0][j];
        d_off[(b*18 + co0 + j)*HW + (ya+1)*WW + x] = acc[1][j];
    }
}

// ---------------- deform conv: fp16 bilinear sample + fp16 mma ---------------
__global__ void deform_mma(const float* __restrict__ dbias) {
    __shared__ unsigned Ssu[128*36];                  // sampled [pix][c/2] half2
    __shared__ unsigned Wsu[64*36];                   // weights [o][c/2] half2
    int b = blockIdx.y;
    int y = blockIdx.x;
    int t = threadIdx.x;                              // 256
    int warp = t >> 5, lane = t & 31;
    int g = lane >> 2, tg = lane & 3;
    int wm = warp & 3, wn = warp >> 2;

    float4 acc[2][4];
#pragma unroll
    for (int i = 0; i < 2; ++i)
#pragma unroll
        for (int j = 0; j < 4; ++j) acc[i][j] = make_float4(0.f,0.f,0.f,0.f);

    const float* offb = d_off + (size_t)b*18*HW + y*WW;
    const __half* xcb = d_xc + (size_t)b*HW*64;
    int pix = t >> 1, half = t & 1;

    for (int k = 0; k < 9; ++k) {
        if (k) __syncthreads();
#pragma unroll
        for (int i = 0; i < 2; ++i) {
            int idx = t + i*256;                      // < 512
            int n = idx >> 3, c16 = idx & 7;
            uint4 v = *(const uint4*)(d_wt + k*4096 + n*64 + c16*8);
            *(uint4*)(Wsu + n*36 + c16*4) = v;
        }
        {
            int x = pix;
            float dy = offb[(2*k  )*HW + x];
            float dx = offb[(2*k+1)*HW + x];
            float py = (float)(y + k/3 - 1) + dy;
            float px = (float)(x + k%3 - 1) + dx;
            float fy = floorf(py), fx = floorf(px);
            float wy = py - fy, wx = px - fx;
            int iy = (int)fy, ix = (int)fx;
            bool y0ok = (iy >= 0)  && (iy < HH);
            bool y1ok = (iy >= -1) && (iy < HH-1);
            bool x0ok = (ix >= 0)  && (ix < WW);
            bool x1ok = (ix >= -1) && (ix < WW-1);
            float w00 = (1.f-wy)*(1.f-wx), w01 = (1.f-wy)*wx;
            float w10 = wy*(1.f-wx),       w11 = wy*wx;
            const __half* r00 = xcb + ((size_t)iy*WW + ix)*64 + half*32;
            const __half* r01 = r00 + 64;
            const __half* r10 = r00 + WW*64;
            const __half* r11 = r10 + 64;
            unsigned* dst = Ssu + pix*36 + half*16;
            uint4 z4 = make_uint4(0,0,0,0);
#pragma unroll
            for (int c8 = 0; c8 < 4; ++c8) {          // 8 channels per iter
                uint4 q00 = (y0ok && x0ok) ? *(const uint4*)(r00 + c8*8) : z4;
                uint4 q01 = (y0ok && x1ok) ? *(const uint4*)(r01 + c8*8) : z4;
                uint4 q10 = (y1ok && x0ok) ? *(const uint4*)(r10 + c8*8) : z4;
                uint4 q11 = (y1ok && x1ok) ? *(const uint4*)(r11 + c8*8) : z4;
                const __half2* h00 = (const __half2*)&q00;
                const __half2* h01 = (const __half2*)&q01;
                const __half2* h10 = (const __half2*)&q10;
                const __half2* h11 = (const __half2*)&q11;
#pragma unroll
                for (int u = 0; u < 4; ++u) {
                    float2 f00 = __half22float2(h00[u]);
                    float2 f01 = __half22float2(h01[u]);
                    float2 f10 = __half22float2(h10[u]);
                    float2 f11 = __half22float2(h11[u]);
                    dst[c8*4 + u] = packh2(
                        w00*f00.x + w01*f01.x + w10*f10.x + w11*f11.x,
                        w00*f00.y + w01*f01.y + w10*f10.y + w11*f11.y);
                }
            }
        }
        __syncthreads();
#pragma unroll
        for (int ks = 0; ks < 4; ++ks) {
            int kk = ks*8;                            // half2 units (16 halves)
            unsigned a[2][4];
#pragma unroll
            for (int i = 0; i < 2; ++i) {
                int row = wm*32 + i*16 + g;
                a[i][0] = Ssu[row*36 + kk + tg];
                a[i][1] = Ssu[(row+8)*36 + kk + tg];
                a[i][2] = Ssu[row*36 + kk + tg + 4];
                a[i][3] = Ssu[(row+8)*36 + kk + tg + 4];
            }
#pragma unroll
            for (int j = 0; j < 4; ++j) {
                int col = wn*32 + j*8 + g;
                unsigned b0 = Wsu[col*36 + kk + tg];
                unsigned b1 = Wsu[col*36 + kk + tg + 4];
                mma16(acc[0][j], a[0], b0, b1);
                mma16(acc[1][j], a[1], b0, b1);
            }
        }
    }
    __half* outb = d_xd + ((size_t)b*HW + y*WW)*64;
#pragma unroll
    for (int i = 0; i < 2; ++i) {
        int row = wm*32 + i*16 + g;
#pragma unroll
        for (int j = 0; j < 4; ++j) {
            int col = wn*32 + j*8 + 2*tg;
            float bx = dbias[col], by = dbias[col+1];
            *(__half2*)(outb + row*64 + col)     = __floats2half2_rn(acc[i][j].x + bx, acc[i][j].y + by);
            *(__half2*)(outb + (row+8)*64 + col) = __floats2half2_rn(acc[i][j].z + bx, acc[i][j].w + by);
        }
    }
}

// ---------------- expand GEMM core (fp16 mma, zero-convert staging) ----------
__device__ __forceinline__ void expand_core16(
    unsigned* Xsu, unsigned* Wsu, float4 acc[2][4],
    int b, int gI, int p0, int t)
{
    int warp = t >> 5, lane = t & 31;
    int g = lane >> 2, tg = lane & 3;
    int wm = warp & 3, wn = warp >> 2;
#pragma unroll
    for (int i = 0; i < 4; ++i) {
        int idx = t + i*256;
        int row = idx >> 3, c16 = idx & 7;
        uint4 q = *(const uint4*)(d_xd + ((size_t)b*HW + p0 + row)*64 + c16*8);
        *(uint4*)(Xsu + row*36 + c16*4) = q;
    }
#pragma unroll
    for (int i = 0; i < 2; ++i) {
        int idx = t + i*256;
        int n = idx >> 3, c16 = idx & 7;
        uint4 v = *(const uint4*)(d_we + (size_t)(gI*64 + n)*64 + c16*8);
        *(uint4*)(Wsu + n*36 + c16*4) = v;
    }
    __syncthreads();
#pragma unroll
    for (int i = 0; i < 2; ++i)
#pragma unroll
        for (int j = 0; j < 4; ++j) acc[i][j] = make_float4(0.f,0.f,0.f,0.f);
#pragma unroll
    for (int ks = 0; ks < 4; ++ks) {
        int kk = ks*8;
        unsigned a[2][4];
#pragma unroll
        for (int i = 0; i < 2; ++i) {
            int row = wm*32 + i*16 + g;
            a[i][0] = Xsu[row*36 + kk + tg];
            a[i][1] = Xsu[(row+8)*36 + kk + tg];
            a[i][2] = Xsu[row*36 + kk + tg + 4];
            a[i][3] = Xsu[(row+8)*36 + kk + tg + 4];
        }
#pragma unroll
        for (int j = 0; j < 4; ++j) {
            int col = wn*32 + j*8 + g;
            unsigned b0 = Wsu[col*36 + kk + tg];
            unsigned b1 = Wsu[col*36 + kk + tg + 4];
            mma16(acc[0][j], a[0], b0, b1);
            mma16(acc[1][j], a[1], b0, b1);
        }
    }
}

// ---------------- expand pass 1: GN partial stats only -----------------------
__global__ void expand_stats(const float* __restrict__ bias) {
    __shared__ unsigned Xsu[128*36];
    __shared__ unsigned Wsu[64*36];
    __shared__ float red[512];
    int tileI = blockIdx.x, gI = blockIdx.y, b = blockIdx.z;
    int p0 = tileI * 128;
    int t = threadIdx.x;                              // 256
    int warp = t >> 5, lane = t & 31;
    int tg = lane & 3;
    int wn = warp >> 2;

    float4 acc[2][4];
    expand_core16(Xsu, Wsu, acc, b, gI, p0, t);

    float lsum = 0.f, lssq = 0.f;
#pragma unroll
    for (int i = 0; i < 2; ++i) {
#pragma unroll
        for (int j = 0; j < 4; ++j) {
            int col = wn*32 + j*8 + 2*tg;
            float bx = bias[gI*64 + col], by = bias[gI*64 + col + 1];
            float v0 = acc[i][j].x + bx, v1 = acc[i][j].y + by;
            float v2 = acc[i][j].z + bx, v3 = acc[i][j].w + by;
            lsum += v0 + v1 + v2 + v3;
            lssq += v0*v0 + v1*v1 + v2*v2 + v3*v3;
        }
    }
    red[t] = lsum; red[256 + t] = lssq;
    __syncthreads();
    for (int s = 128; s > 0; s >>= 1) {
        if (t < s) { red[t] += red[t+s]; red[256+t] += red[256+t+s]; }
        __syncthreads();
    }
    if (t == 0) {
        int bg = b*4 + gI;
        d_part[(bg*128 + tileI)*2 + 0] = red[0];
        d_part[(bg*128 + tileI)*2 + 1] = red[256];
    }
}

// ---------------- GN stats finalize ------------------------------------------
__global__ void gn_finalize_kernel() {
    __shared__ float red[256];
    int bg = blockIdx.x;
    int t = threadIdx.x;                              // 128
    red[t]       = d_part[(bg*128 + t)*2 + 0];
    red[128 + t] = d_part[(bg*128 + t)*2 + 1];
    __syncthreads();
    for (int s = 64; s > 0; s >>= 1) {
        if (t < s) { red[t] += red[t+s]; red[128+t] += red[128+t+s]; }
        __syncthreads();
    }
    if (t == 0) {
        const float N = 64.0f * (float)HW;
        float mean = red[0] / N;
        float var = red[128] / N - mean*mean;
        var = fmaxf(var, 0.f);
        d_mv[bg*2 + 0] = mean;
        d_mv[bg*2 + 1] = rsqrtf(var + 1e-5f);
    }
}

// ------- expand pass 2: recompute + GN + gelu + residual -> out --------------
__global__ void expand_apply(const float* __restrict__ bias,
                             const float* __restrict__ feat,
                             const float* __restrict__ gamma,
                             const float* __restrict__ beta,
                             float* __restrict__ out) {
    __shared__ unsigned Buf[128*68];                  // Xsu (front) / OutS overlay
    __shared__ unsigned Wsu[64*36];
    __shared__ float ga_s[64], be_s[64];
    int tileI = blockIdx.x, gI = blockIdx.y, b = blockIdx.z;
    int p0 = tileI * 128;
    int t = threadIdx.x;                              // 256
    int warp = t >> 5, lane = t & 31;
    int g = lane >> 2, tg = lane & 3;
    int wm = warp & 3, wn = warp >> 2;

    float4 acc[2][4];
    expand_core16(Buf, Wsu, acc, b, gI, p0, t);

    if (t < 64) {
        int bg = b*4 + gI;
        float mean = d_mv[bg*2], rstd = d_mv[bg*2 + 1];
        float gaf = gamma[gI*64 + t];
        ga_s[t] = gaf * rstd;
        be_s[t] = beta[gI*64 + t] - mean * rstd * gaf;
    }
    __syncthreads();                                  // Buf/Wsu reads done

    float* OutS = (float*)Buf;                        // [pix][co] pad 65
#pragma unroll
    for (int i = 0; i < 2; ++i) {
        int row = wm*32 + i*16 + g;
#pragma unroll
        for (int j = 0; j < 4; ++j) {
            int col = wn*32 + j*8 + 2*tg;
            float bx = bias[gI*64 + col], by = bias[gI*64 + col + 1];
            OutS[row*65 + col]       = acc[i][j].x + bx;
            OutS[row*65 + col + 1]   = acc[i][j].y + by;
            OutS[(row+8)*65 + col]   = acc[i][j].z + bx;
            OutS[(row+8)*65 + col+1] = acc[i][j].w + by;
        }
    }
    __syncthreads();

    const float* fb = feat + ((size_t)b*CC + gI*64)*HW + p0;
    float* ob = out + ((size_t)b*CC + gI*64)*HW + p0;
#pragma unroll
    for (int i = 0; i < 8; ++i) {
        int e4 = t + i*256;                           // < 2048 float4
        int co = e4 >> 5, px = (e4 & 31)*4;
        float4 f = *(const float4*)(fb + (size_t)co*HW + px);
        float ga = ga_s[co], be = be_s[co];
        float4 o;
        o.x = f.x + gelu_exact(OutS[(px  )*65 + co]*ga + be);
        o.y = f.y + gelu_exact(OutS[(px+1)*65 + co]*ga + be);
        o.z = f.z + gelu_exact(OutS[(px+2)*65 + co]*ga + be);
        o.w = f.w + gelu_exact(OutS[(px+3)*65 + co]*ga + be);
        *(float4*)(ob + (size_t)co*HW + px) = o;
    }
}

// ---------------- launch ------------------------------------------------------
extern "C" void kernel_launch(void* const* d_in, const int* in_sizes, int n_in,
                              void* d_out, int out_size) {
    const float* features   = (const float*)d_in[0];
    const float* wind_uv    = (const float*)d_in[1];
    const float* compress_w = (const float*)d_in[2];
    const float* compress_b = (const float*)d_in[3];
    const float* off1_w     = (const float*)d_in[4];
    const float* off1_b     = (const float*)d_in[5];
    const float* off2_w     = (const float*)d_in[6];
    const float* off2_b     = (const float*)d_in[7];
    const float* deform_w   = (const float*)d_in[8];
    const float* deform_b   = (const float*)d_in[9];
    const float* expand_w   = (const float*)d_in[10];
    const float* expand_b   = (const float*)d_in[11];
    const float* gn_gamma   = (const float*)d_in[12];
    const float* gn_beta    = (const float*)d_in[13];
    float* out = (float*)d_out;

    prep_w_kernel<<<208, 256>>>(deform_w, expand_w);
    compress_mma16<<<dim3(128, 8), 256>>>(features, compress_w, compress_b);
    off1_v2<<<dim3(128, 8), 128>>>(wind_uv, off1_w, off1_b);
    off2_v5<<<dim3(64, 8), 256>>>(off2_w, off2_b);
    deform_mma<<<dim3(128, 8), 256>>>(deform_b);
    expand_stats<<<dim3(128, 4, 8), 256>>>(expand_b);
    gn_finalize_kernel<<<32, 128>>>();
    expand_apply<<<dim3(128, 4, 8), 256>>>(expand_b, features,
                                           gn_gamma, gn_beta, out);
}

// round 16
// speedup vs baseline: 1.1005x; 1.1005x over previous
#include <cuda_runtime.h>
#include <cuda_fp16.h>
#include <math.h>

#define BB 8
#define CC 256
#define MID 64
#define HH 128
#define WW 128
#define HW 16384

// ---------------- scratch (static device arrays; no allocations) -------------
__device__ __half d_xc[BB*HW*MID];      // compress out, channels-last fp16
__device__ float d_h [BB*32*HW];        // off1 out (gelu'd) [b][32][H][W]
__device__ float d_off[BB*18*HW];       // offsets [b][18][H][W]
__device__ __half d_xd[BB*HW*MID];      // deform out, channels-last fp16
__device__ __half d_wt[9*MID*MID];      // deform weight [k][o][c], fp16
__device__ __half d_we[CC*MID];         // expand weight [n][k], fp16
__device__ float d_part[BB*4*128*2];    // GN partial (sum,sumsq) per (b,g,tile)
__device__ float d_mv[BB*4*2];          // GN (mean, rstd) per (b,g)

__device__ __forceinline__ float gelu_exact(float v) {
    return 0.5f * v * (1.0f + erff(v * 0.70710678118654752440f));
}

__device__ __forceinline__ unsigned packh2(float a, float b) {
    __half2 h = __floats2half2_rn(a, b);
    return *(unsigned*)&h;
}

__device__ __forceinline__ void mma16(float4& d, const unsigned* a, unsigned b0, unsigned b1) {
    asm volatile(
        "mma.sync.aligned.m16n8k16.row.col.f32.f16.f16.f32 "
        "{%0,%1,%2,%3}, {%4,%5,%6,%7}, {%8,%9}, {%0,%1,%2,%3};\n"
        : "+f"(d.x), "+f"(d.y), "+f"(d.z), "+f"(d.w)
        : "r"(a[0]), "r"(a[1]), "r"(a[2]), "r"(a[3]), "r"(b0), "r"(b1));
}

// ===== K1: fused weight-prep (blocks 512..719) + off1 (blocks 0..511) ========
__global__ void k1_prep_off1(const float* __restrict__ wd,
                             const float* __restrict__ we,
                             const float* __restrict__ wind,
                             const float* __restrict__ w1,
                             const float* __restrict__ b1) {
    __shared__ float pool[1040 + 576];                // off1: tile + weights
    int bid = blockIdx.x;
    int t = threadIdx.x;                              // 256

    if (bid >= 512) {                                 // ---- prep part ----
        int e = (bid - 512) * 256 + t;                // < 53248
        if (e < 36864) {
            int k = e >> 12;
            int rem = e & 4095;
            int o = rem >> 6;
            int c = rem & 63;
            d_wt[e] = __float2half(wd[(o*64 + c)*9 + k]);
        } else {
            int i = e - 36864;                        // < 16384
            d_we[i] = __float2half(we[i]);
        }
        return;
    }

    // ---- off1 part: 2 rows per block, 256 threads (1 px/thread) ----
    float* tile = pool;                               // [ci][ry 0..3][130]
    float* wsm  = pool + 1040;                        // [k18][co32]
    int b = bid >> 6;
    int y0 = (bid & 63) * 2;
    for (int e = t; e < 576; e += 256) {
        int co = e / 18, rem = e % 18;
        wsm[rem*32 + co] = w1[e];
    }
    for (int e = t; e < 1040; e += 256) {
        int ci = e / 520, rem = e % 520;
        int ry = rem / 130, col = rem % 130;
        int yy = y0 - 1 + ry, xx = col - 1;
        float v = 0.f;
        if (yy >= 0 && yy < HH && xx >= 0 && xx < WW)
            v = wind[(b*2 + ci)*HW + yy*WW + xx];
        tile[e] = v;
    }
    __syncthreads();
    int yl = t >> 7, x = t & 127;
    float acc[32];
#pragma unroll
    for (int j = 0; j < 32; ++j) acc[j] = b1[j];
#pragma unroll
    for (int ci = 0; ci < 2; ++ci)
#pragma unroll
        for (int ky = 0; ky < 3; ++ky)
#pragma unroll
            for (int kx = 0; kx < 3; ++kx) {
                float v = tile[ci*520 + (yl + ky)*130 + x + kx];
                const float* wp = wsm + (ci*9 + ky*3 + kx)*32;
#pragma unroll
                for (int j = 0; j < 32; ++j) acc[j] += v * wp[j];
            }
    int y = y0 + yl;
#pragma unroll
    for (int j = 0; j < 32; ++j)
        d_h[(b*32 + j)*HW + y*WW + x] = gelu_exact(acc[j]);
}

// ===== K2: fused off2_v3 (blocks 0..255) + compress (blocks 256..1279) =======
__global__ void __launch_bounds__(256, 3)
k2_compress_off2(const float* __restrict__ feat,
                 const float* __restrict__ cw,
                 const float* __restrict__ cb,
                 const float* __restrict__ w2,
                 const float* __restrict__ b2) {
    __shared__ float pool[12000];                     // 48000 B union
    int bid = blockIdx.x;
    int t = threadIdx.x;                              // 256
    int warp = t >> 5, lane = t & 31;
    int g = lane >> 2, tg = lane & 3;
    int wm = warp & 3, wn = warp >> 2;

    if (bid < 256) {
        // ---------------- off2_v3 body ----------------
        float* wsm  = pool;                           // [288][20]
        float* tile = pool + 5760;                    // [8][6][130]
        int b = bid >> 5;
        int y0 = (bid & 31) * 4;
        int yp = t >> 7, x = t & 127;

        for (int e = t; e < 5184; e += 256) {
            int co = e / 288, rem = e % 288;
            wsm[rem*20 + co] = w2[e];
        }
        float acc[2][18];
#pragma unroll
        for (int j = 0; j < 18; ++j) { acc[0][j] = b2[j]; acc[1][j] = b2[j]; }

        for (int ch = 0; ch < 4; ++ch) {
            __syncthreads();
            for (int e = t; e < 6240; e += 256) {
                int cil = e / 780, rem = e % 780;
                int ry = rem / 130, col = rem % 130;
                int yy = y0 - 1 + ry, xx = col - 1;
                float v = 0.f;
                if (yy >= 0 && yy < HH && xx >= 0 && xx < WW)
                    v = d_h[((b*32 + ch*8 + cil)*HW) + yy*WW + xx];
                tile[e] = v;
            }
            __syncthreads();
            for (int cil = 0; cil < 8; ++cil) {
#pragma unroll
                for (int ky = 0; ky < 3; ++ky) {
                    const float* base = tile + cil*780 + (yp*2 + ky)*130 + x;
                    float a0 = base[0],   a1 = base[1],   a2 = base[2];
                    float b0 = base[130], b1 = base[131], b2v = base[132];
                    const float* w0 = wsm + ((ch*8 + cil)*9 + ky*3)*20;
#pragma unroll
                    for (int j = 0; j < 18; ++j) {
                        float wa = w0[j], wb = w0[20 + j], wc = w0[40 + j];
                        acc[0][j] += a0*wa + a1*wb + a2*wc;
                        acc[1][j] += b0*wa + b1*wb + b2v*wc;
                    }
                }
            }
        }
        int ya = y0 + yp*2;
#pragma unroll
        for (int j = 0; j < 18; ++j) {
            d_off[(b*18 + j)*HW + ya*WW + x]     = acc[0][j];
            d_off[(b*18 + j)*HW + (ya+1)*WW + x] = acc[1][j];
        }
        return;
    }

    // ---------------- compress body ----------------
    unsigned* Asu = (unsigned*)pool;                  // [16][132] half2
    unsigned* Bsu = (unsigned*)pool + 16*132;         // [64][20] half2
    int cid = bid - 256;
    int b = cid >> 7;
    int p0 = (cid & 127) * 128;

    float4 acc[2][4];
#pragma unroll
    for (int i = 0; i < 2; ++i)
#pragma unroll
        for (int j = 0; j < 4; ++j) acc[i][j] = make_float4(0.f,0.f,0.f,0.f);

    const float* fb = feat + (size_t)b*CC*HW + p0;
    for (int kb = 0; kb < 8; ++kb) {
        __syncthreads();
#pragma unroll
        for (int i = 0; i < 2; ++i) {
            int idx = t + i*256;                      // < 512
            int k2 = idx >> 5, mg = idx & 31;
            const float* r0 = fb + (size_t)(kb*32 + 2*k2)*HW + mg*4;
            float4 v0 = *(const float4*)r0;
            float4 v1 = *(const float4*)(r0 + HW);
            uint4 pk;
            pk.x = packh2(v0.x, v1.x);
            pk.y = packh2(v0.y, v1.y);
            pk.z = packh2(v0.z, v1.z);
            pk.w = packh2(v0.w, v1.w);
            *(uint4*)(Asu + k2*132 + mg*4) = pk;
        }
#pragma unroll
        for (int i = 0; i < 2; ++i) {
            int idx = t + i*256;                      // < 512
            int kq = idx & 7, n = idx >> 3;
            float4 v = *(const float4*)(cw + n*256 + kb*32 + kq*4);
            uint2 pk2;
            pk2.x = packh2(v.x, v.y);
            pk2.y = packh2(v.z, v.w);
            *(uint2*)(Bsu + n*20 + kq*2) = pk2;
        }
        __syncthreads();
#pragma unroll
        for (int ks = 0; ks < 2; ++ks) {
            int kk2 = ks*8;
            unsigned a[2][4];
#pragma unroll
            for (int i = 0; i < 2; ++i) {
                int row = wm*32 + i*16 + g;
                a[i][0] = Asu[(kk2+tg  )*132 + row];
                a[i][1] = Asu[(kk2+tg  )*132 + row + 8];
                a[i][2] = Asu[(kk2+tg+4)*132 + row];
                a[i][3] = Asu[(kk2+tg+4)*132 + row + 8];
            }
#pragma unroll
            for (int j = 0; j < 4; ++j) {
                int col = wn*32 + j*8 + g;
                unsigned b0 = Bsu[col*20 + kk2 + tg];
                unsigned b1 = Bsu[col*20 + kk2 + tg + 4];
                mma16(acc[0][j], a[0], b0, b1);
                mma16(acc[1][j], a[1], b0, b1);
            }
        }
    }
    __half* outb = d_xc + ((size_t)b*HW + p0)*64;
#pragma unroll
    for (int i = 0; i < 2; ++i) {
        int row = wm*32 + i*16 + g;
#pragma unroll
        for (int j = 0; j < 4; ++j) {
            int col = wn*32 + j*8 + 2*tg;
            float bx = cb[col], by = cb[col+1];
            *(__half2*)(outb + row*64 + col)     = __floats2half2_rn(acc[i][j].x + bx, acc[i][j].y + by);
            *(__half2*)(outb + (row+8)*64 + col) = __floats2half2_rn(acc[i][j].z + bx, acc[i][j].w + by);
        }
    }
}

// ---------------- deform conv: fp16 bilinear sample + fp16 mma ---------------
__global__ void deform_mma(const float* __restrict__ dbias) {
    __shared__ unsigned Ssu[128*36];                  // sampled [pix][c/2] half2
    __shared__ unsigned Wsu[64*36];                   // weights [o][c/2] half2
    int b = blockIdx.y;
    int y = blockIdx.x;
    int t = threadIdx.x;                              // 256
    int warp = t >> 5, lane = t & 31;
    int g = lane >> 2, tg = lane & 3;
    int wm = warp & 3, wn = warp >> 2;

    float4 acc[2][4];
#pragma unroll
    for (int i = 0; i < 2; ++i)
#pragma unroll
        for (int j = 0; j < 4; ++j) acc[i][j] = make_float4(0.f,0.f,0.f,0.f);

    const float* offb = d_off + (size_t)b*18*HW + y*WW;
    const __half* xcb = d_xc + (size_t)b*HW*64;
    int pix = t >> 1, half = t & 1;

    for (int k = 0; k < 9; ++k) {
        if (k) __syncthreads();
#pragma unroll
        for (int i = 0; i < 2; ++i) {
            int idx = t + i*256;                      // < 512
            int n = idx >> 3, c16 = idx & 7;
            uint4 v = *(const uint4*)(d_wt + k*4096 + n*64 + c16*8);
            *(uint4*)(Wsu + n*36 + c16*4) = v;
        }
        {
            int x = pix;
            float dy = offb[(2*k  )*HW + x];
            float dx = offb[(2*k+1)*HW + x];
            float py = (float)(y + k/3 - 1) + dy;
            float px = (float)(x + k%3 - 1) + dx;
            float fy = floorf(py), fx = floorf(px);
            float wy = py - fy, wx = px - fx;
            int iy = (int)fy, ix = (int)fx;
            bool y0ok = (iy >= 0)  && (iy < HH);
            bool y1ok = (iy >= -1) && (iy < HH-1);
            bool x0ok = (ix >= 0)  && (ix < WW);
            bool x1ok = (ix >= -1) && (ix < WW-1);
            float w00 = (1.f-wy)*(1.f-wx), w01 = (1.f-wy)*wx;
            float w10 = wy*(1.f-wx),       w11 = wy*wx;
            const __half* r00 = xcb + ((size_t)iy*WW + ix)*64 + half*32;
            const __half* r01 = r00 + 64;
            const __half* r10 = r00 + WW*64;
            const __half* r11 = r10 + 64;
            unsigned* dst = Ssu + pix*36 + half*16;
            uint4 z4 = make_uint4(0,0,0,0);
#pragma unroll
            for (int c8 = 0; c8 < 4; ++c8) {          // 8 channels per iter
                uint4 q00 = (y0ok && x0ok) ? *(const uint4*)(r00 + c8*8) : z4;
                uint4 q01 = (y0ok && x1ok) ? *(const uint4*)(r01 + c8*8) : z4;
                uint4 q10 = (y1ok && x0ok) ? *(const uint4*)(r10 + c8*8) : z4;
                uint4 q11 = (y1ok && x1ok) ? *(const uint4*)(r11 + c8*8) : z4;
                const __half2* h00 = (const __half2*)&q00;
                const __half2* h01 = (const __half2*)&q01;
                const __half2* h10 = (const __half2*)&q10;
                const __half2* h11 = (const __half2*)&q11;
#pragma unroll
                for (int u = 0; u < 4; ++u) {
                    float2 f00 = __half22float2(h00[u]);
                    float2 f01 = __half22float2(h01[u]);
                    float2 f10 = __half22float2(h10[u]);
                    float2 f11 = __half22float2(h11[u]);
                    dst[c8*4 + u] = packh2(
                        w00*f00.x + w01*f01.x + w10*f10.x + w11*f11.x,
                        w00*f00.y + w01*f01.y + w10*f10.y + w11*f11.y);
                }
            }
        }
        __syncthreads();
#pragma unroll
        for (int ks = 0; ks < 4; ++ks) {
            int kk = ks*8;                            // half2 units (16 halves)
            unsigned a[2][4];
#pragma unroll
            for (int i = 0; i < 2; ++i) {
                int row = wm*32 + i*16 + g;
                a[i][0] = Ssu[row*36 + kk + tg];
                a[i][1] = Ssu[(row+8)*36 + kk + tg];
                a[i][2] = Ssu[row*36 + kk + tg + 4];
                a[i][3] = Ssu[(row+8)*36 + kk + tg + 4];
            }
#pragma unroll
            for (int j = 0; j < 4; ++j) {
                int col = wn*32 + j*8 + g;
                unsigned b0 = Wsu[col*36 + kk + tg];
                unsigned b1 = Wsu[col*36 + kk + tg + 4];
                mma16(acc[0][j], a[0], b0, b1);
                mma16(acc[1][j], a[1], b0, b1);
            }
        }
    }
    __half* outb = d_xd + ((size_t)b*HW + y*WW)*64;
#pragma unroll
    for (int i = 0; i < 2; ++i) {
        int row = wm*32 + i*16 + g;
#pragma unroll
        for (int j = 0; j < 4; ++j) {
            int col = wn*32 + j*8 + 2*tg;
            float bx = dbias[col], by = dbias[col+1];
            *(__half2*)(outb + row*64 + col)     = __floats2half2_rn(acc[i][j].x + bx, acc[i][j].y + by);
            *(__half2*)(outb + (row+8)*64 + col) = __floats2half2_rn(acc[i][j].z + bx, acc[i][j].w + by);
        }
    }
}

// ---------------- expand GEMM core (fp16 mma, zero-convert staging) ----------
__device__ __forceinline__ void expand_core16(
    unsigned* Xsu, unsigned* Wsu, float4 acc[2][4],
    int b, int gI, int p0, int t)
{
    int warp = t >> 5, lane = t & 31;
    int g = lane >> 2, tg = lane & 3;
    int wm = warp & 3, wn = warp >> 2;
#pragma unroll
    for (int i = 0; i < 4; ++i) {
        int idx = t + i*256;
        int row = idx >> 3, c16 = idx & 7;
        uint4 q = *(const uint4*)(d_xd + ((size_t)b*HW + p0 + row)*64 + c16*8);
        *(uint4*)(Xsu + row*36 + c16*4) = q;
    }
#pragma unroll
    for (int i = 0; i < 2; ++i) {
        int idx = t + i*256;
        int n = idx >> 3, c16 = idx & 7;
        uint4 v = *(const uint4*)(d_we + (size_t)(gI*64 + n)*64 + c16*8);
        *(uint4*)(Wsu + n*36 + c16*4) = v;
    }
    __syncthreads();
#pragma unroll
    for (int i = 0; i < 2; ++i)
#pragma unroll
        for (int j = 0; j < 4; ++j) acc[i][j] = make_float4(0.f,0.f,0.f,0.f);
#pragma unroll
    for (int ks = 0; ks < 4; ++ks) {
        int kk = ks*8;
        unsigned a[2][4];
#pragma unroll
        for (int i = 0; i < 2; ++i) {
            int row = wm*32 + i*16 + g;
            a[i][0] = Xsu[row*36 + kk + tg];
            a[i][1] = Xsu[(row+8)*36 + kk + tg];
            a[i][2] = Xsu[row*36 + kk + tg + 4];
            a[i][3] = Xsu[(row+8)*36 + kk + tg + 4];
        }
#pragma unroll
        for (int j = 0; j < 4; ++j) {
            int col = wn*32 + j*8 + g;
            unsigned b0 = Wsu[col*36 + kk + tg];
            unsigned b1 = Wsu[col*36 + kk + tg + 4];
            mma16(acc[0][j], a[0], b0, b1);
            mma16(acc[1][j], a[1], b0, b1);
        }
    }
}

// ---------------- expand pass 1: GN partial stats only -----------------------
__global__ void expand_stats(const float* __restrict__ bias) {
    __shared__ unsigned Xsu[128*36];
    __shared__ unsigned Wsu[64*36];
    __shared__ float red[512];
    int tileI = blockIdx.x, gI = blockIdx.y, b = blockIdx.z;
    int p0 = tileI * 128;
    int t = threadIdx.x;                              // 256
    int warp = t >> 5, lane = t & 31;
    int tg = lane & 3;
    int wn = warp >> 2;

    float4 acc[2][4];
    expand_core16(Xsu, Wsu, acc, b, gI, p0, t);

    float lsum = 0.f, lssq = 0.f;
#pragma unroll
    for (int i = 0; i < 2; ++i) {
#pragma unroll
        for (int j = 0; j < 4; ++j) {
            int col = wn*32 + j*8 + 2*tg;
            float bx = bias[gI*64 + col], by = bias[gI*64 + col + 1];
            float v0 = acc[i][j].x + bx, v1 = acc[i][j].y + by;
            float v2 = acc[i][j].z + bx, v3 = acc[i][j].w + by;
            lsum += v0 + v1 + v2 + v3;
            lssq += v0*v0 + v1*v1 + v2*v2 + v3*v3;
        }
    }
    red[t] = lsum; red[256 + t] = lssq;
    __syncthreads();
    for (int s = 128; s > 0; s >>= 1) {
        if (t < s) { red[t] += red[t+s]; red[256+t] += red[256+t+s]; }
        __syncthreads();
    }
    if (t == 0) {
        int bg = b*4 + gI;
        d_part[(bg*128 + tileI)*2 + 0] = red[0];
        d_part[(bg*128 + tileI)*2 + 1] = red[256];
    }
}

// ---------------- GN stats finalize ------------------------------------------
__global__ void gn_finalize_kernel() {
    __shared__ float red[256];
    int bg = blockIdx.x;
    int t = threadIdx.x;                              // 128
    red[t]       = d_part[(bg*128 + t)*2 + 0];
    red[128 + t] = d_part[(bg*128 + t)*2 + 1];
    __syncthreads();
    for (int s = 64; s > 0; s >>= 1) {
        if (t < s) { red[t] += red[t+s]; red[128+t] += red[128+t+s]; }
        __syncthreads();
    }
    if (t == 0) {
        const float N = 64.0f * (float)HW;
        float mean = red[0] / N;
        float var = red[128] / N - mean*mean;
        var = fmaxf(var, 0.f);
        d_mv[bg*2 + 0] = mean;
        d_mv[bg*2 + 1] = rsqrtf(var + 1e-5f);
    }
}

// ------- expand pass 2: recompute + GN + gelu + residual -> out --------------
__global__ void expand_apply(const float* __restrict__ bias,
                             const float* __restrict__ feat,
                             const float* __restrict__ gamma,
                             const float* __restrict__ beta,
                             float* __restrict__ out) {
    __shared__ unsigned Buf[128*68];                  // Xsu (front) / OutS overlay
    __shared__ unsigned Wsu[64*36];
    __shared__ float ga_s[64], be_s[64];
    int tileI = blockIdx.x, gI = blockIdx.y, b = blockIdx.z;
    int p0 = tileI * 128;
    int t = threadIdx.x;                              // 256
    int warp = t >> 5, lane = t & 31;
    int g = lane >> 2, tg = lane & 3;
    int wm = warp & 3, wn = warp >> 2;

    float4 acc[2][4];
    expand_core16(Buf, Wsu, acc, b, gI, p0, t);

    if (t < 64) {
        int bg = b*4 + gI;
        float mean = d_mv[bg*2], rstd = d_mv[bg*2 + 1];
        float gaf = gamma[gI*64 + t];
        ga_s[t] = gaf * rstd;
        be_s[t] = beta[gI*64 + t] - mean * rstd * gaf;
    }
    __syncthreads();                                  // Buf/Wsu reads done

    float* OutS = (float*)Buf;                        // [pix][co] pad 65
#pragma unroll
    for (int i = 0; i < 2; ++i) {
        int row = wm*32 + i*16 + g;
#pragma unroll
        for (int j = 0; j < 4; ++j) {
            int col = wn*32 + j*8 + 2*tg;
            float bx = bias[gI*64 + col], by = bias[gI*64 + col + 1];
            OutS[row*65 + col]       = acc[i][j].x + bx;
            OutS[row*65 + col + 1]   = acc[i][j].y + by;
            OutS[(row+8)*65 + col]   = acc[i][j].z + bx;
            OutS[(row+8)*65 + col+1] = acc[i][j].w + by;
        }
    }
    __syncthreads();

    const float* fb = feat + ((size_t)b*CC + gI*64)*HW + p0;
    float* ob = out + ((size_t)b*CC + gI*64)*HW + p0;
#pragma unroll
    for (int i = 0; i < 8; ++i) {
        int e4 = t + i*256;                           // < 2048 float4
        int co = e4 >> 5, px = (e4 & 31)*4;
        float4 f = *(const float4*)(fb + (size_t)co*HW + px);
        float ga = ga_s[co], be = be_s[co];
        float4 o;
        o.x = f.x + gelu_exact(OutS[(px  )*65 + co]*ga + be);
        o.y = f.y + gelu_exact(OutS[(px+1)*65 + co]*ga + be);
        o.z = f.z + gelu_exact(OutS[(px+2)*65 + co]*ga + be);
        o.w = f.w + gelu_exact(OutS[(px+3)*65 + co]*ga + be);
        *(float4*)(ob + (size_t)co*HW + px) = o;
    }
}

// ---------------- launch ------------------------------------------------------
extern "C" void kernel_launch(void* const* d_in, const int* in_sizes, int n_in,
                              void* d_out, int out_size) {
    const float* features   = (const float*)d_in[0];
    const float* wind_uv    = (const float*)d_in[1];
    const float* compress_w = (const float*)d_in[2];
    const float* compress_b = (const float*)d_in[3];
    const float* off1_w     = (const float*)d_in[4];
    const float* off1_b     = (const float*)d_in[5];
    const float* off2_w     = (const float*)d_in[6];
    const float* off2_b     = (const float*)d_in[7];
    const float* deform_w   = (const float*)d_in[8];
    const float* deform_b   = (const float*)d_in[9];
    const float* expand_w   = (const float*)d_in[10];
    const float* expand_b   = (const float*)d_in[11];
    const float* gn_gamma   = (const float*)d_in[12];
    const float* gn_beta    = (const float*)d_in[13];
    float* out = (float*)d_out;

    k1_prep_off1<<<720, 256>>>(deform_w, expand_w, wind_uv, off1_w, off1_b);
    k2_compress_off2<<<1280, 256>>>(features, compress_w, compress_b,
                                    off2_w, off2_b);
    deform_mma<<<dim3(128, 8), 256>>>(deform_b);
    expand_stats<<<dim3(128, 4, 8), 256>>>(expand_b);
    gn_finalize_kernel<<<32, 128>>>();
    expand_apply<<<dim3(128, 4, 8), 256>>>(expand_b, features,
                                           gn_gamma, gn_beta, out);
}